// round 5
// baseline (speedup 1.0000x reference)
#include <cuda_runtime.h>
#include <cuda_bf16.h>
#include <math.h>
#include <stdint.h>

#define B_  8
#define S_  512
#define D_  1024
#define H_  16
#define DH_ 64
#define BH_ 128

// ---------------- scratch (device globals; no runtime allocation) ----------------
__device__ float g_att[(size_t)B_*S_*D_];             // attention out, concat [B,S,D]
__device__ float g_dv [(size_t)B_*S_*S_];             // exp(sigmoid(pdiff)), 8 MB (L2-resident)
__device__ __nv_bfloat16 g_qhh[(size_t)BH_*S_*DH_], g_qhl[(size_t)BH_*S_*DH_];
__device__ __nv_bfloat16 g_khh[(size_t)BH_*S_*DH_], g_khl[(size_t)BH_*S_*DH_];
__device__ __nv_bfloat16 g_vhh[(size_t)BH_*S_*DH_], g_vhl[(size_t)BH_*S_*DH_];

// ======================= warp-level bf16 MMA ======================================
__device__ __forceinline__ void mma_bf16(float* c, uint32_t a0, uint32_t a1,
                                         uint32_t a2, uint32_t a3,
                                         uint32_t b0, uint32_t b1) {
    asm volatile(
        "mma.sync.aligned.m16n8k16.row.col.f32.bf16.bf16.f32 "
        "{%0,%1,%2,%3}, {%4,%5,%6,%7}, {%8,%9}, {%0,%1,%2,%3};"
        : "+f"(c[0]), "+f"(c[1]), "+f"(c[2]), "+f"(c[3])
        : "r"(a0), "r"(a1), "r"(a2), "r"(a3), "r"(b0), "r"(b1));
}
__device__ __forceinline__ uint32_t pack_bf16(float x, float y) {
    __nv_bfloat162 t = __floats2bfloat162_rn(x, y);
    return *(uint32_t*)&t;
}
__device__ __forceinline__ void split4(float4 v, uint32_t& h0, uint32_t& h1,
                                       uint32_t& l0, uint32_t& l1) {
    h0 = pack_bf16(v.x, v.y);
    h1 = pack_bf16(v.z, v.w);
    __nv_bfloat162 hh0 = *(__nv_bfloat162*)&h0;
    __nv_bfloat162 hh1 = *(__nv_bfloat162*)&h1;
    l0 = pack_bf16(v.x - __bfloat162float(hh0.x), v.y - __bfloat162float(hh0.y));
    l1 = pack_bf16(v.z - __bfloat162float(hh1.x), v.w - __bfloat162float(hh1.y));
}

// ==================================================================================
// Double-buffered bf16x3 GEMM:  C = A[M,K] * W[N,K]^T + bias   (unchanged from R4)
// ==================================================================================
#define PADW 20
#define STG  10240

template<bool PAIR>
__device__ __forceinline__ void gemm_body(const float* __restrict__ A,
                                          const float* __restrict__ W,
                                          const float* __restrict__ bias,
                                          float* outF, __nv_bfloat16* outH,
                                          __nv_bfloat16* outL,
                                          int m0, int n0, uint32_t* dsm)
{
    int tid = threadIdx.x, lane = tid & 31, wid = tid >> 5;
    int wm = wid >> 2, wn = wid & 3;
    int lq = lane >> 2, tq = lane & 3;

    float acc[4][4][4];
    #pragma unroll
    for (int mt = 0; mt < 4; mt++)
        #pragma unroll
        for (int nt = 0; nt < 4; nt++)
            #pragma unroll
            for (int e = 0; e < 4; e++) acc[mt][nt][e] = 0.f;

    int rowr[4], cqr[4], wofs[4];
    #pragma unroll
    for (int r = 0; r < 4; r++) {
        int g = tid + r * 256;
        rowr[r] = g >> 3;
        cqr[r]  = g & 7;
        wofs[r] = rowr[r] * PADW + cqr[r] * 2;
    }

    float4 va[4], vb[4];
    #pragma unroll
    for (int r = 0; r < 4; r++) {
        va[r] = *(const float4*)(A + (size_t)(m0 + rowr[r]) * D_ + cqr[r] * 4);
        vb[r] = *(const float4*)(W + (size_t)(n0 + rowr[r]) * D_ + cqr[r] * 4);
    }

    auto cvtstore = [&](uint32_t* base) {
        #pragma unroll
        for (int r = 0; r < 4; r++) {
            uint32_t h0, h1, l0, l1;
            split4(va[r], h0, h1, l0, l1);
            base[wofs[r]]        = h0; base[wofs[r] + 1]        = h1;
            base[2560 + wofs[r]] = l0; base[2560 + wofs[r] + 1] = l1;
            split4(vb[r], h0, h1, l0, l1);
            base[5120 + wofs[r]] = h0; base[5120 + wofs[r] + 1] = h1;
            base[7680 + wofs[r]] = l0; base[7680 + wofs[r] + 1] = l1;
        }
    };

    cvtstore(dsm);
    int stage = 0;

    for (int kc = 0; kc < 32; kc++) {
        __syncthreads();
        if (kc < 31) {
            int k0 = (kc + 1) * 32;
            #pragma unroll
            for (int r = 0; r < 4; r++) {
                va[r] = *(const float4*)(A + (size_t)(m0 + rowr[r]) * D_ + k0 + cqr[r] * 4);
                vb[r] = *(const float4*)(W + (size_t)(n0 + rowr[r]) * D_ + k0 + cqr[r] * 4);
            }
        }
        uint32_t* base = dsm + stage * STG;
        #pragma unroll
        for (int ks = 0; ks < 2; ks++) {
            int kofs = ks * 8 + tq;
            uint32_t bh[4][2], bl[4][2];
            #pragma unroll
            for (int nt = 0; nt < 4; nt++) {
                int bi = (wn * 32 + nt * 8 + lq) * PADW + kofs;
                bh[nt][0] = base[5120 + bi]; bh[nt][1] = base[5120 + bi + 4];
                bl[nt][0] = base[7680 + bi]; bl[nt][1] = base[7680 + bi + 4];
            }
            #pragma unroll
            for (int mt = 0; mt < 4; mt++) {
                int ai = (wm * 64 + mt * 16 + lq) * PADW + kofs;
                uint32_t ah0 = base[ai],            ah1 = base[ai + 8 * PADW];
                uint32_t ah2 = base[ai + 4],        ah3 = base[ai + 8 * PADW + 4];
                uint32_t al0 = base[2560 + ai],     al1 = base[2560 + ai + 8 * PADW];
                uint32_t al2 = base[2560 + ai + 4], al3 = base[2560 + ai + 8 * PADW + 4];
                #pragma unroll
                for (int nt = 0; nt < 4; nt++) {
                    mma_bf16(acc[mt][nt], ah0, ah1, ah2, ah3, bh[nt][0], bh[nt][1]);
                    mma_bf16(acc[mt][nt], ah0, ah1, ah2, ah3, bl[nt][0], bl[nt][1]);
                    mma_bf16(acc[mt][nt], al0, al1, al2, al3, bh[nt][0], bh[nt][1]);
                }
            }
        }
        if (kc < 31) cvtstore(dsm + (stage ^ 1) * STG);
        stage ^= 1;
    }

    #pragma unroll
    for (int mt = 0; mt < 4; mt++) {
        #pragma unroll
        for (int nt = 0; nt < 4; nt++) {
            int n = n0 + wn * 32 + nt * 8 + tq * 2;
            float b0v = __ldg(bias + n), b1v = __ldg(bias + n + 1);
            #pragma unroll
            for (int hf = 0; hf < 2; hf++) {
                int m = m0 + wm * 64 + mt * 16 + lq + hf * 8;
                float v0 = acc[mt][nt][hf * 2 + 0] + b0v;
                float v1 = acc[mt][nt][hf * 2 + 1] + b1v;
                if (PAIR) {
                    int bb = m / S_, srow = m % S_;
                    int h = n >> 6, d = n & 63;
                    size_t idx = (((size_t)bb * H_ + h) * S_ + srow) * DH_ + d;
                    __nv_bfloat16 h0 = __float2bfloat16(v0);
                    __nv_bfloat16 h1 = __float2bfloat16(v1);
                    __nv_bfloat162 hv; hv.x = h0; hv.y = h1;
                    __nv_bfloat162 lv;
                    lv.x = __float2bfloat16(v0 - __bfloat162float(h0));
                    lv.y = __float2bfloat16(v1 - __bfloat162float(h1));
                    *(__nv_bfloat162*)(outH + idx) = hv;
                    *(__nv_bfloat162*)(outL + idx) = lv;
                } else {
                    *(float2*)&outF[(size_t)m * D_ + n] = make_float2(v0, v1);
                }
            }
        }
    }
}

__global__ __launch_bounds__(256, 1)
void gemm_qkv(const float* __restrict__ q, const float* __restrict__ k,
              const float* __restrict__ v, const float* __restrict__ Wk,
              const float* __restrict__ bk, const float* __restrict__ Wv,
              const float* __restrict__ bv)
{
    extern __shared__ __align__(16) uint32_t dsm[];
    int z = blockIdx.z;
    const float* A    = (z == 0) ? q : (z == 1) ? k : v;
    const float* W    = (z == 2) ? Wv : Wk;
    const float* bias = (z == 2) ? bv : bk;
    __nv_bfloat16* oh = (z == 0) ? g_qhh : (z == 1) ? g_khh : g_vhh;
    __nv_bfloat16* ol = (z == 0) ? g_qhl : (z == 1) ? g_khl : g_vhl;
    gemm_body<true>(A, W, bias, nullptr, oh, ol,
                    blockIdx.y * 128, blockIdx.x * 128, dsm);
}

__global__ __launch_bounds__(256, 1)
void gemm_out(const float* __restrict__ A, const float* __restrict__ W,
              const float* __restrict__ bias, float* __restrict__ out)
{
    extern __shared__ __align__(16) uint32_t dsm[];
    gemm_body<false>(A, W, bias, out, nullptr, nullptr,
                     blockIdx.y * 128, blockIdx.x * 128, dsm);
}

// ==================================================================================
// dv precompute: dv[b,i,j] = exp(sigmoid(pdiff))  (8 MB, L2-resident afterwards)
// ==================================================================================
__global__ __launch_bounds__(256)
void dv_kernel(const float* __restrict__ pdiff)
{
    size_t idx = (size_t)blockIdx.x * 256 + threadIdx.x;
    float x = pdiff[idx];
    float sig = 1.f / (1.f + __expf(-x));
    g_dv[idx] = __expf(sig);
}

// ==================================================================================
// FUSED attention: scores (QK^T MMA) -> row ops -> PV MMA, all in one CTA.
// CTA = (head z, 64-row query block rb). Scores live in SMEM fp32 (never gmem).
// SMEM: sS 64x516 fp32 (132KB) + union{ Q/K bf16 tiles | P/V bf16 tiles } (70KB).
// ==================================================================================
#define SPITCH 516
#define PADS   36
#define PVP    68    // words per row, P/V phase-B tiles

__global__ __launch_bounds__(256, 1)
void fused_attn(const float* __restrict__ gammas)
{
    extern __shared__ __align__(16) float sS[];           // 64*516 words
    uint32_t* u = (uint32_t*)(sS + 64 * SPITCH);
    // phase A
    uint32_t* sQh = u;                  // 64*36  = 2304
    uint32_t* sQl = u + 2304;
    uint32_t* sKh = u + 4608;           // 128*36 = 4608
    uint32_t* sKl = u + 9216;
    // phase B (aliases phase A)
    uint32_t* sPh = u;                  // 64*68 = 4352
    uint32_t* sPl = u + 4352;
    uint32_t* sVh = u + 8704;
    uint32_t* sVl = u + 13056;
    __nv_bfloat16* sVh16 = (__nv_bfloat16*)sVh;
    __nv_bfloat16* sVl16 = (__nv_bfloat16*)sVl;

    int z  = blockIdx.y;
    int rb = 7 - (int)blockIdx.x;        // heavy blocks first
    int b  = z >> 4, h = z & 15;
    int i0 = rb * 64;
    int nck = rb / 2 + 1;                // 128-col chunks needed (causal)

    int tid = threadIdx.x, lane = tid & 31, wid = tid >> 5;
    int wm = wid >> 2, wn = wid & 3, lq = lane >> 2, tq = lane & 3;

    // ---- load Q tile (64 rows x 32 words) into pitch-36 SMEM ----
    {
        int row = tid >> 2;
        int w0  = (tid & 3) * 8;
        const uint32_t* qh = (const uint32_t*)g_qhh + ((size_t)z * S_ + i0 + row) * 32 + w0;
        const uint32_t* ql = (const uint32_t*)g_qhl + ((size_t)z * S_ + i0 + row) * 32 + w0;
        int so = row * PADS + w0;
        uint4 a = *(const uint4*)qh, bb2 = *(const uint4*)(qh + 4);
        *(uint4*)(sQh + so) = a; *(uint4*)(sQh + so + 4) = bb2;
        a = *(const uint4*)ql; bb2 = *(const uint4*)(ql + 4);
        *(uint4*)(sQl + so) = a; *(uint4*)(sQl + so + 4) = bb2;
    }

    // ================= phase 1: scores into sS =================
    for (int cn = 0; cn < nck; cn++) {
        int j0 = cn * 128;
        {   // load K chunk (128 rows x 32 words)
            int row = tid >> 1;
            int w0  = (tid & 1) * 16;
            const uint32_t* kh = (const uint32_t*)g_khh + ((size_t)z * S_ + j0 + row) * 32 + w0;
            const uint32_t* kl = (const uint32_t*)g_khl + ((size_t)z * S_ + j0 + row) * 32 + w0;
            int so = row * PADS + w0;
            #pragma unroll
            for (int qd = 0; qd < 4; qd++) {
                *(uint4*)(sKh + so + qd * 4) = *(const uint4*)(kh + qd * 4);
                *(uint4*)(sKl + so + qd * 4) = *(const uint4*)(kl + qd * 4);
            }
        }
        __syncthreads();

        float acc[2][4][4];
        #pragma unroll
        for (int mt = 0; mt < 2; mt++)
            #pragma unroll
            for (int nt = 0; nt < 4; nt++)
                #pragma unroll
                for (int e = 0; e < 4; e++) acc[mt][nt][e] = 0.f;

        #pragma unroll
        for (int ks = 0; ks < 4; ks++) {
            int kofs = ks * 8 + tq;
            uint32_t bh[4][2], bl[4][2];
            #pragma unroll
            for (int nt = 0; nt < 4; nt++) {
                int bi = (wn * 32 + nt * 8 + lq) * PADS + kofs;
                bh[nt][0] = sKh[bi]; bh[nt][1] = sKh[bi + 4];
                bl[nt][0] = sKl[bi]; bl[nt][1] = sKl[bi + 4];
            }
            #pragma unroll
            for (int mt = 0; mt < 2; mt++) {
                int ai = (wm * 32 + mt * 16 + lq) * PADS + kofs;
                uint32_t ah0 = sQh[ai],     ah1 = sQh[ai + 8 * PADS];
                uint32_t ah2 = sQh[ai + 4], ah3 = sQh[ai + 8 * PADS + 4];
                uint32_t al0 = sQl[ai],     al1 = sQl[ai + 8 * PADS];
                uint32_t al2 = sQl[ai + 4], al3 = sQl[ai + 8 * PADS + 4];
                #pragma unroll
                for (int nt = 0; nt < 4; nt++) {
                    mma_bf16(acc[mt][nt], ah0, ah1, ah2, ah3, bh[nt][0], bh[nt][1]);
                    mma_bf16(acc[mt][nt], ah0, ah1, ah2, ah3, bl[nt][0], bl[nt][1]);
                    mma_bf16(acc[mt][nt], al0, al1, al2, al3, bh[nt][0], bh[nt][1]);
                }
            }
        }

        #pragma unroll
        for (int mt = 0; mt < 2; mt++) {
            #pragma unroll
            for (int nt = 0; nt < 4; nt++) {
                int j = j0 + wn * 32 + nt * 8 + tq * 2;
                #pragma unroll
                for (int hf = 0; hf < 2; hf++) {
                    int il = wm * 32 + mt * 16 + lq + hf * 8;
                    *(float2*)&sS[il * SPITCH + j] =
                        make_float2(acc[mt][nt][hf * 2] * 0.125f,
                                    acc[mt][nt][hf * 2 + 1] * 0.125f);
                }
            }
        }
        __syncthreads();
    }

    // ================= phase 2: row ops in SMEM (warp per row, 8 rows/warp) ======
    float gma = gammas[h];
    float gamma = -log1pf(__expf(gma));   // -softplus

    for (int r8 = 0; r8 < 8; r8++) {
        int il = wid * 8 + r8;
        int im = i0 + il;
        float* srow = sS + il * SPITCH;
        const float* dvrow = g_dv + ((size_t)b * S_ + im) * S_;
        int nch = (im >> 5) + 1;

        float scv[16], s2v[16];
        // pass 1: load + exp (no max shift; scores bounded) + inclusive scan
        float run = 0.f;
        #pragma unroll
        for (int c = 0; c < 16; c++) {
            if (c < nch) {
                int j = c * 32 + lane;
                float v = srow[j];
                scv[c] = v;
                float p = (j <= im) ? __expf(v) : 0.f;
                float s = p;
                #pragma unroll
                for (int d = 1; d < 32; d <<= 1) {
                    float t = __shfl_up_sync(0xFFFFFFFFu, s, d);
                    if (lane >= d) s += t;
                }
                s2v[c] = run + s;
                run += __shfl_sync(0xFFFFFFFFu, s, 31);
            }
        }
        float tot  = run;
        float rtot = 1.f / fmaxf(tot, 1e-30f);

        // pass 2: decay reweight + exp (eff<=1 so s2 bounded) + sum
        float sum2 = 0.f;
        #pragma unroll
        for (int c = 0; c < 16; c++) {
            if (c < nch) {
                int j = c * 32 + lane;
                float rem  = fmaxf(tot - s2v[c], 0.f) * rtot;
                float pos  = (float)(im - j);
                float dist = sqrtf(fmaxf(rem * pos, 0.f));
                float dv   = dvrow[j];
                float eff  = __expf(dist * gamma * dv);
                eff = fminf(fmaxf(eff, 1e-5f), 1e5f);
                float s2 = scv[c] * eff;
                float e2 = (j <= im) ? __expf(s2) : 0.f;
                s2v[c] = e2;
                sum2 += e2;
            }
        }
        #pragma unroll
        for (int o = 16; o > 0; o >>= 1) sum2 += __shfl_xor_sync(0xFFFFFFFFu, sum2, o);
        float rs = (im == 0) ? 0.f : 1.f / sum2;

        // pass 3: write normalized P back; zero-fill to 128-chunk boundary
        int nwrite = nck * 4;
        #pragma unroll
        for (int c = 0; c < 16; c++) {
            int j = c * 32 + lane;
            if (c < nch)          srow[j] = (j <= im) ? s2v[c] * rs : 0.f;
            else if (c < nwrite)  srow[j] = 0.f;
        }
    }
    __syncthreads();

    // ================= phase 3: PV MMA, chunked over k =================
    float pacc[2][2][4];
    #pragma unroll
    for (int mt = 0; mt < 2; mt++)
        #pragma unroll
        for (int nt = 0; nt < 2; nt++)
            #pragma unroll
            for (int e = 0; e < 4; e++) pacc[mt][nt][e] = 0.f;

    for (int cn = 0; cn < nck; cn++) {
        int k0 = cn * 128;
        __syncthreads();   // prev MMA done before overwriting sPh/sV

        {   // convert P chunk fp32 -> bf16 hi/lo (64 rows x 128 cols)
            int row = tid >> 2;
            int c0  = (tid & 3) * 32;
            const float* src = sS + row * SPITCH + k0 + c0;
            uint32_t* dh = sPh + row * PVP + (c0 >> 1);
            uint32_t* dl = sPl + row * PVP + (c0 >> 1);
            #pragma unroll
            for (int w = 0; w < 8; w++) {
                float4 v = *(const float4*)(src + w * 4);
                uint32_t h0, h1, l0, l1;
                split4(v, h0, h1, l0, l1);
                dh[w * 2] = h0; dh[w * 2 + 1] = h1;
                dl[w * 2] = l0; dl[w * 2 + 1] = l1;
            }
        }
        {   // load V chunk transposed: sVt[d][k_local], pitch 68 words (136 bf16)
            int r  = tid >> 1;             // 0..127 = k_local
            int w0 = (tid & 1) * 16;
            const uint32_t* vh = (const uint32_t*)g_vhh + ((size_t)z * S_ + k0 + r) * 32 + w0;
            const uint32_t* vl = (const uint32_t*)g_vhl + ((size_t)z * S_ + k0 + r) * 32 + w0;
            #pragma unroll
            for (int qd = 0; qd < 4; qd++) {
                uint4 vv = *(const uint4*)(vh + qd * 4);
                uint32_t wv[4] = {vv.x, vv.y, vv.z, vv.w};
                #pragma unroll
                for (int q2 = 0; q2 < 4; q2++) {
                    int d0 = (w0 + qd * 4 + q2) * 2;
                    __nv_bfloat162 pr = *(__nv_bfloat162*)&wv[q2];
                    sVh16[d0 * 136 + r]       = pr.x;
                    sVh16[(d0 + 1) * 136 + r] = pr.y;
                }
                vv = *(const uint4*)(vl + qd * 4);
                wv[0] = vv.x; wv[1] = vv.y; wv[2] = vv.z; wv[3] = vv.w;
                #pragma unroll
                for (int q2 = 0; q2 < 4; q2++) {
                    int d0 = (w0 + qd * 4 + q2) * 2;
                    __nv_bfloat162 pr = *(__nv_bfloat162*)&wv[q2];
                    sVl16[d0 * 136 + r]       = pr.x;
                    sVl16[(d0 + 1) * 136 + r] = pr.y;
                }
            }
        }
        __syncthreads();

        #pragma unroll
        for (int ks = 0; ks < 8; ks++) {
            int kofs = ks * 8 + tq;
            uint32_t bh[2][2], bl[2][2];
            #pragma unroll
            for (int nt = 0; nt < 2; nt++) {
                int bi = (wn * 16 + nt * 8 + lq) * PVP + kofs;
                bh[nt][0] = sVh[bi]; bh[nt][1] = sVh[bi + 4];
                bl[nt][0] = sVl[bi]; bl[nt][1] = sVl[bi + 4];
            }
            #pragma unroll
            for (int mt = 0; mt < 2; mt++) {
                int ai = (wm * 32 + mt * 16 + lq) * PVP + kofs;
                uint32_t ah0 = sPh[ai],     ah1 = sPh[ai + 8 * PVP];
                uint32_t ah2 = sPh[ai + 4], ah3 = sPh[ai + 8 * PVP + 4];
                uint32_t al0 = sPl[ai],     al1 = sPl[ai + 8 * PVP];
                uint32_t al2 = sPl[ai + 4], al3 = sPl[ai + 8 * PVP + 4];
                #pragma unroll
                for (int nt = 0; nt < 2; nt++) {
                    mma_bf16(pacc[mt][nt], ah0, ah1, ah2, ah3, bh[nt][0], bh[nt][1]);
                    mma_bf16(pacc[mt][nt], al0, al1, al2, al3, bh[nt][0], bh[nt][1]);
                    mma_bf16(pacc[mt][nt], ah0, ah1, ah2, ah3, bl[nt][0], bl[nt][1]);
                }
            }
        }
    }

    #pragma unroll
    for (int mt = 0; mt < 2; mt++) {
        #pragma unroll
        for (int nt = 0; nt < 2; nt++) {
            int d = wn * 16 + nt * 8 + tq * 2;
            #pragma unroll
            for (int hf = 0; hf < 2; hf++) {
                int i = i0 + wm * 32 + mt * 16 + lq + hf * 8;
                *(float2*)&g_att[((size_t)b * S_ + i) * D_ + h * DH_ + d] =
                    make_float2(pacc[mt][nt][hf * 2], pacc[mt][nt][hf * 2 + 1]);
            }
        }
    }
}

// ==================================================================================
extern "C" void kernel_launch(void* const* d_in, const int* in_sizes, int n_in,
                              void* d_out, int out_size)
{
    const float* q      = (const float*)d_in[0];
    const float* k      = (const float*)d_in[1];
    const float* v      = (const float*)d_in[2];
    const float* pdiff  = (const float*)d_in[3];
    const float* Wk     = (const float*)d_in[4];
    const float* bk     = (const float*)d_in[5];
    const float* Wv     = (const float*)d_in[6];
    const float* bv     = (const float*)d_in[7];
    const float* Wo     = (const float*)d_in[8];
    const float* bo     = (const float*)d_in[9];
    const float* gammas = (const float*)d_in[10];
    float* out = (float*)d_out;

    float* att;
    cudaGetSymbolAddress((void**)&att, g_att);

    const int FUSED_SMEM = (64 * SPITCH + 17408) * 4;   // 201728 B

    cudaFuncSetAttribute(gemm_qkv,   cudaFuncAttributeMaxDynamicSharedMemorySize, 81920);
    cudaFuncSetAttribute(gemm_out,   cudaFuncAttributeMaxDynamicSharedMemorySize, 81920);
    cudaFuncSetAttribute(fused_attn, cudaFuncAttributeMaxDynamicSharedMemorySize, FUSED_SMEM);

    gemm_qkv<<<dim3(8, 32, 3), 256, 81920>>>(q, k, v, Wk, bk, Wv, bv);

    dv_kernel<<<(B_ * S_ * S_) / 256, 256>>>(pdiff);

    fused_attn<<<dim3(8, BH_), 256, FUSED_SMEM>>>(gammas);

    gemm_out<<<dim3(8, 32), 256, 81920>>>(att, Wo, bo, out);
}

// round 6
// speedup vs baseline: 1.2521x; 1.2521x over previous
#include <cuda_runtime.h>
#include <cuda_bf16.h>
#include <math.h>
#include <stdint.h>

#define B_  8
#define S_  512
#define D_  1024
#define H_  16
#define DH_ 64
#define BH_ 128

// ---------------- scratch (device globals; no runtime allocation) ----------------
__device__ float g_sc [(size_t)BH_*S_*S_];            // fp32 scores
__device__ float g_att[(size_t)B_*S_*D_];             // attention out, concat [B,S,D]
__device__ float g_dv [(size_t)B_*S_*S_];             // exp(sigmoid(pdiff))
__device__ __nv_bfloat16 g_qhh[(size_t)BH_*S_*DH_], g_qhl[(size_t)BH_*S_*DH_];
__device__ __nv_bfloat16 g_khh[(size_t)BH_*S_*DH_], g_khl[(size_t)BH_*S_*DH_];
__device__ __nv_bfloat16 g_vhh[(size_t)BH_*S_*DH_], g_vhl[(size_t)BH_*S_*DH_];
__device__ __nv_bfloat16 g_phi[(size_t)BH_*S_*S_],  g_plo[(size_t)BH_*S_*S_];

// ======================= warp-level bf16 MMA ======================================
__device__ __forceinline__ void mma_bf16(float* c, uint32_t a0, uint32_t a1,
                                         uint32_t a2, uint32_t a3,
                                         uint32_t b0, uint32_t b1) {
    asm volatile(
        "mma.sync.aligned.m16n8k16.row.col.f32.bf16.bf16.f32 "
        "{%0,%1,%2,%3}, {%4,%5,%6,%7}, {%8,%9}, {%0,%1,%2,%3};"
        : "+f"(c[0]), "+f"(c[1]), "+f"(c[2]), "+f"(c[3])
        : "r"(a0), "r"(a1), "r"(a2), "r"(a3), "r"(b0), "r"(b1));
}
__device__ __forceinline__ uint32_t pack_bf16(float x, float y) {
    __nv_bfloat162 t = __floats2bfloat162_rn(x, y);
    return *(uint32_t*)&t;
}
__device__ __forceinline__ void split4(float4 v, uint32_t& h0, uint32_t& h1,
                                       uint32_t& l0, uint32_t& l1) {
    h0 = pack_bf16(v.x, v.y);
    h1 = pack_bf16(v.z, v.w);
    __nv_bfloat162 hh0 = *(__nv_bfloat162*)&h0;
    __nv_bfloat162 hh1 = *(__nv_bfloat162*)&h1;
    l0 = pack_bf16(v.x - __bfloat162float(hh0.x), v.y - __bfloat162float(hh0.y));
    l1 = pack_bf16(v.z - __bfloat162float(hh1.x), v.w - __bfloat162float(hh1.y));
}

// ==================================================================================
// bf16x3 GEMM, occupancy-2:  C = A[M,K] * W[N,K]^T + bias
// Block 64(M) x 128(N), BK=32, 8 warps (2x4), warp tile 32x32, double-buffered.
// Per-stage SMEM (words, PADW=20): Ah 0, Al 1280, Bh 2560, Bl 5120; stage = 7680.
// 60 KB dynamic SMEM per CTA -> 2 CTAs/SM; __launch_bounds__(256,2) caps regs.
// ==================================================================================
#define PADW 20
#define STG2 7680

template<bool PAIR>
__device__ __forceinline__ void gemm_body(const float* __restrict__ A,
                                          const float* __restrict__ W,
                                          const float* __restrict__ bias,
                                          float* outF, __nv_bfloat16* outH,
                                          __nv_bfloat16* outL,
                                          int m0, int n0, uint32_t* dsm)
{
    int tid = threadIdx.x, lane = tid & 31, wid = tid >> 5;
    int wm = wid >> 2, wn = wid & 3;
    int lq = lane >> 2, tq = lane & 3;

    float acc[2][4][4];
    #pragma unroll
    for (int mt = 0; mt < 2; mt++)
        #pragma unroll
        for (int nt = 0; nt < 4; nt++)
            #pragma unroll
            for (int e = 0; e < 4; e++) acc[mt][nt][e] = 0.f;

    // A: 512 float4 slots (2/thread); B: 1024 slots (4/thread)
    int arow[2], acq[2], aof[2];
    #pragma unroll
    for (int r = 0; r < 2; r++) {
        int g = tid + r * 256;
        arow[r] = g >> 3; acq[r] = g & 7;
        aof[r] = arow[r] * PADW + acq[r] * 2;
    }
    int brow[4], bcq[4], bof[4];
    #pragma unroll
    for (int r = 0; r < 4; r++) {
        int g = tid + r * 256;
        brow[r] = g >> 3; bcq[r] = g & 7;
        bof[r] = brow[r] * PADW + bcq[r] * 2;
    }

    float4 va[2], vb[4];
    #pragma unroll
    for (int r = 0; r < 2; r++)
        va[r] = *(const float4*)(A + (size_t)(m0 + arow[r]) * D_ + acq[r] * 4);
    #pragma unroll
    for (int r = 0; r < 4; r++)
        vb[r] = *(const float4*)(W + (size_t)(n0 + brow[r]) * D_ + bcq[r] * 4);

    auto cvtstore = [&](uint32_t* base) {
        #pragma unroll
        for (int r = 0; r < 2; r++) {
            uint32_t h0, h1, l0, l1;
            split4(va[r], h0, h1, l0, l1);
            base[aof[r]]        = h0; base[aof[r] + 1]        = h1;
            base[1280 + aof[r]] = l0; base[1280 + aof[r] + 1] = l1;
        }
        #pragma unroll
        for (int r = 0; r < 4; r++) {
            uint32_t h0, h1, l0, l1;
            split4(vb[r], h0, h1, l0, l1);
            base[2560 + bof[r]] = h0; base[2560 + bof[r] + 1] = h1;
            base[5120 + bof[r]] = l0; base[5120 + bof[r] + 1] = l1;
        }
    };

    cvtstore(dsm);
    int stage = 0;

    for (int kc = 0; kc < 32; kc++) {
        __syncthreads();
        if (kc < 31) {
            int k0 = (kc + 1) * 32;
            #pragma unroll
            for (int r = 0; r < 2; r++)
                va[r] = *(const float4*)(A + (size_t)(m0 + arow[r]) * D_ + k0 + acq[r] * 4);
            #pragma unroll
            for (int r = 0; r < 4; r++)
                vb[r] = *(const float4*)(W + (size_t)(n0 + brow[r]) * D_ + k0 + bcq[r] * 4);
        }
        uint32_t* base = dsm + stage * STG2;
        #pragma unroll
        for (int ks = 0; ks < 2; ks++) {
            int kofs = ks * 8 + tq;
            uint32_t bh[4][2], bl[4][2];
            #pragma unroll
            for (int nt = 0; nt < 4; nt++) {
                int bi = 2560 + (wn * 32 + nt * 8 + lq) * PADW + kofs;
                bh[nt][0] = base[bi];        bh[nt][1] = base[bi + 4];
                bl[nt][0] = base[bi + 2560]; bl[nt][1] = base[bi + 2560 + 4];
            }
            #pragma unroll
            for (int mt = 0; mt < 2; mt++) {
                int ai = (wm * 32 + mt * 16 + lq) * PADW + kofs;
                uint32_t ah0 = base[ai],            ah1 = base[ai + 8 * PADW];
                uint32_t ah2 = base[ai + 4],        ah3 = base[ai + 8 * PADW + 4];
                uint32_t al0 = base[1280 + ai],     al1 = base[1280 + ai + 8 * PADW];
                uint32_t al2 = base[1280 + ai + 4], al3 = base[1280 + ai + 8 * PADW + 4];
                #pragma unroll
                for (int nt = 0; nt < 4; nt++) {
                    mma_bf16(acc[mt][nt], ah0, ah1, ah2, ah3, bh[nt][0], bh[nt][1]);
                    mma_bf16(acc[mt][nt], ah0, ah1, ah2, ah3, bl[nt][0], bl[nt][1]);
                    mma_bf16(acc[mt][nt], al0, al1, al2, al3, bh[nt][0], bh[nt][1]);
                }
            }
        }
        if (kc < 31) cvtstore(dsm + (stage ^ 1) * STG2);
        stage ^= 1;
    }

    #pragma unroll
    for (int mt = 0; mt < 2; mt++) {
        #pragma unroll
        for (int nt = 0; nt < 4; nt++) {
            int n = n0 + wn * 32 + nt * 8 + tq * 2;
            float b0v = __ldg(bias + n), b1v = __ldg(bias + n + 1);
            #pragma unroll
            for (int hf = 0; hf < 2; hf++) {
                int m = m0 + wm * 32 + mt * 16 + lq + hf * 8;
                float v0 = acc[mt][nt][hf * 2 + 0] + b0v;
                float v1 = acc[mt][nt][hf * 2 + 1] + b1v;
                if (PAIR) {
                    int bb = m / S_, srow = m % S_;
                    int h = n >> 6, d = n & 63;
                    size_t idx = (((size_t)bb * H_ + h) * S_ + srow) * DH_ + d;
                    __nv_bfloat16 h0 = __float2bfloat16(v0);
                    __nv_bfloat16 h1 = __float2bfloat16(v1);
                    __nv_bfloat162 hv; hv.x = h0; hv.y = h1;
                    __nv_bfloat162 lv;
                    lv.x = __float2bfloat16(v0 - __bfloat162float(h0));
                    lv.y = __float2bfloat16(v1 - __bfloat162float(h1));
                    *(__nv_bfloat162*)(outH + idx) = hv;
                    *(__nv_bfloat162*)(outL + idx) = lv;
                } else {
                    *(float2*)&outF[(size_t)m * D_ + n] = make_float2(v0, v1);
                }
            }
        }
    }
}

__global__ __launch_bounds__(256, 2)
void gemm_qkv(const float* __restrict__ q, const float* __restrict__ k,
              const float* __restrict__ v, const float* __restrict__ Wk,
              const float* __restrict__ bk, const float* __restrict__ Wv,
              const float* __restrict__ bv)
{
    extern __shared__ __align__(16) uint32_t dsm[];
    int z = blockIdx.z;
    const float* A    = (z == 0) ? q : (z == 1) ? k : v;
    const float* W    = (z == 2) ? Wv : Wk;
    const float* bias = (z == 2) ? bv : bk;
    __nv_bfloat16* oh = (z == 0) ? g_qhh : (z == 1) ? g_khh : g_vhh;
    __nv_bfloat16* ol = (z == 0) ? g_qhl : (z == 1) ? g_khl : g_vhl;
    gemm_body<true>(A, W, bias, nullptr, oh, ol,
                    blockIdx.y * 64, blockIdx.x * 128, dsm);
}

__global__ __launch_bounds__(256, 2)
void gemm_out(const float* __restrict__ A, const float* __restrict__ W,
              const float* __restrict__ bias, float* __restrict__ out)
{
    extern __shared__ __align__(16) uint32_t dsm[];
    gemm_body<false>(A, W, bias, out, nullptr, nullptr,
                     blockIdx.y * 64, blockIdx.x * 128, dsm);
}

// ==================================================================================
// Scores via MMA: per head z, tile 128x128, causal (10 of 16 tiles). (R4, unchanged)
// ==================================================================================
#define PADS 36

__global__ __launch_bounds__(256, 1)
void scores_mma()
{
    extern __shared__ __align__(16) uint32_t sm[];
    uint32_t* sQh = sm;
    uint32_t* sQl = sm + 4608;
    uint32_t* sKh = sm + 9216;
    uint32_t* sKl = sm + 13824;

    int z = blockIdx.y;
    int t = blockIdx.x;
    int mi = (t < 1) ? 0 : (t < 3) ? 1 : (t < 6) ? 2 : 3;
    int ni = t - mi * (mi + 1) / 2;
    int m0 = mi * 128, n0 = ni * 128;

    int tid = threadIdx.x, lane = tid & 31, wid = tid >> 5;
    int wm = wid >> 2, wn = wid & 3, lq = lane >> 2, tq = lane & 3;

    const uint32_t* qh = (const uint32_t*)(g_qhh + (size_t)z * S_ * DH_);
    const uint32_t* ql = (const uint32_t*)(g_qhl + (size_t)z * S_ * DH_);
    const uint32_t* kh = (const uint32_t*)(g_khh + (size_t)z * S_ * DH_);
    const uint32_t* kl = (const uint32_t*)(g_khl + (size_t)z * S_ * DH_);

    {
        int row = tid >> 1, hf = tid & 1;
        int gq = (m0 + row) * 32 + hf * 16;
        int gk = (n0 + row) * 32 + hf * 16;
        int so = row * PADS + hf * 16;
        #pragma unroll
        for (int qd = 0; qd < 4; qd++) {
            *(uint4*)((uint32_t*)sQh + so + qd * 4) = *(const uint4*)(qh + gq + qd * 4);
            *(uint4*)((uint32_t*)sQl + so + qd * 4) = *(const uint4*)(ql + gq + qd * 4);
            *(uint4*)((uint32_t*)sKh + so + qd * 4) = *(const uint4*)(kh + gk + qd * 4);
            *(uint4*)((uint32_t*)sKl + so + qd * 4) = *(const uint4*)(kl + gk + qd * 4);
        }
    }
    __syncthreads();

    float acc[4][4][4];
    #pragma unroll
    for (int mt = 0; mt < 4; mt++)
        #pragma unroll
        for (int nt = 0; nt < 4; nt++)
            #pragma unroll
            for (int e = 0; e < 4; e++) acc[mt][nt][e] = 0.f;

    #pragma unroll
    for (int ks = 0; ks < 4; ks++) {
        int kofs = ks * 8 + tq;
        uint32_t bh[4][2], bl[4][2];
        #pragma unroll
        for (int nt = 0; nt < 4; nt++) {
            int bi = (wn * 32 + nt * 8 + lq) * PADS + kofs;
            bh[nt][0] = sKh[bi]; bh[nt][1] = sKh[bi + 4];
            bl[nt][0] = sKl[bi]; bl[nt][1] = sKl[bi + 4];
        }
        #pragma unroll
        for (int mt = 0; mt < 4; mt++) {
            int ai = (wm * 64 + mt * 16 + lq) * PADS + kofs;
            uint32_t ah0 = sQh[ai],     ah1 = sQh[ai + 8 * PADS];
            uint32_t ah2 = sQh[ai + 4], ah3 = sQh[ai + 8 * PADS + 4];
            uint32_t al0 = sQl[ai],     al1 = sQl[ai + 8 * PADS];
            uint32_t al2 = sQl[ai + 4], al3 = sQl[ai + 8 * PADS + 4];
            #pragma unroll
            for (int nt = 0; nt < 4; nt++) {
                mma_bf16(acc[mt][nt], ah0, ah1, ah2, ah3, bh[nt][0], bh[nt][1]);
                mma_bf16(acc[mt][nt], ah0, ah1, ah2, ah3, bl[nt][0], bl[nt][1]);
                mma_bf16(acc[mt][nt], al0, al1, al2, al3, bh[nt][0], bh[nt][1]);
            }
        }
    }

    float* C = g_sc + (size_t)z * S_ * S_;
    #pragma unroll
    for (int mt = 0; mt < 4; mt++) {
        #pragma unroll
        for (int nt = 0; nt < 4; nt++) {
            int j = n0 + wn * 32 + nt * 8 + tq * 2;
            #pragma unroll
            for (int hf = 0; hf < 2; hf++) {
                int i = m0 + wm * 64 + mt * 16 + lq + hf * 8;
                *(float2*)&C[(size_t)i * S_ + j] =
                    make_float2(acc[mt][nt][hf * 2] * 0.125f,
                                acc[mt][nt][hf * 2 + 1] * 0.125f);
            }
        }
    }
}

// ==================================================================================
// dv precompute
// ==================================================================================
__global__ __launch_bounds__(256)
void dv_kernel(const float* __restrict__ pdiff)
{
    size_t idx = (size_t)blockIdx.x * 256 + threadIdx.x;
    float x = pdiff[idx];
    float sig = 1.f / (1.f + __expf(-x));
    g_dv[idx] = __expf(sig);
}

// ==================================================================================
// Row kernel: warp per row, no max-shift (scores bounded; validated in R5),
// writes P as bf16 hi/lo zero-padded to 128-boundary.
// ==================================================================================
__global__ __launch_bounds__(256)
void row_kernel(const float* __restrict__ gammas)
{
    int warp = threadIdx.x >> 5, lane = threadIdx.x & 31;
    int i = blockIdx.x * 8 + warp;
    int z = blockIdx.y;
    int b = z >> 4, h = z & 15;

    const float* row   = g_sc + ((size_t)z * S_ + i) * S_;
    const float* dvrow = g_dv + ((size_t)b * S_ + i) * S_;

    int nch = (i >> 5) + 1;
    float scv[16], s2v[16];

    // pass 1: load + exp + inclusive scan (no max shift)
    float run = 0.f;
    #pragma unroll
    for (int c = 0; c < 16; c++) {
        if (c < nch) {
            int j = c * 32 + lane;
            float v = row[j];
            scv[c] = v;
            float p = (j <= i) ? __expf(v) : 0.f;
            float s = p;
            #pragma unroll
            for (int d = 1; d < 32; d <<= 1) {
                float tt = __shfl_up_sync(0xFFFFFFFFu, s, d);
                if (lane >= d) s += tt;
            }
            s2v[c] = run + s;
            run += __shfl_sync(0xFFFFFFFFu, s, 31);
        }
    }
    float tot  = run;
    float rtot = 1.f / fmaxf(tot, 1e-30f);

    float g = gammas[h];
    float gamma = -log1pf(__expf(g));

    // pass 2: decay reweight + exp + sum
    float sum2 = 0.f;
    #pragma unroll
    for (int c = 0; c < 16; c++) {
        if (c < nch) {
            int j = c * 32 + lane;
            float rem  = fmaxf(tot - s2v[c], 0.f) * rtot;
            float pos  = (float)(i - j);
            float dist = sqrtf(fmaxf(rem * pos, 0.f));
            float dv   = dvrow[j];
            float eff  = __expf(dist * gamma * dv);
            eff = fminf(fmaxf(eff, 1e-5f), 1e5f);
            float s2 = scv[c] * eff;
            float e2 = (j <= i) ? __expf(s2) : 0.f;
            s2v[c] = e2;
            sum2 += e2;
        }
    }
    #pragma unroll
    for (int o = 16; o > 0; o >>= 1) sum2 += __shfl_xor_sync(0xFFFFFFFFu, sum2, o);

    float rs = (i == 0) ? 0.f : 1.f / sum2;

    __nv_bfloat16* ph = g_phi + ((size_t)z * S_ + i) * S_;
    __nv_bfloat16* pl = g_plo + ((size_t)z * S_ + i) * S_;
    int nwrite = ((i >> 7) + 1) * 4;
    #pragma unroll
    for (int c = 0; c < 16; c++) {
        int j = c * 32 + lane;
        if (c < nch || c < nwrite) {
            float p = (c < nch && j <= i) ? s2v[c] * rs : 0.f;
            __nv_bfloat16 hh = __float2bfloat16(p);
            ph[j] = hh;
            pl[j] = __float2bfloat16(p - __bfloat162float(hh));
        }
    }
}

// ==================================================================================
// PV via MMA (R4, unchanged): out[i,d] = sum_j P[i,j] V[j,d]. 128(M) x 64(N).
// ==================================================================================
__global__ __launch_bounds__(256, 1)
void pv_mma()
{
    extern __shared__ __align__(16) uint32_t sm[];
    uint32_t* sPh = sm;
    uint32_t* sPl = sm + 4608;
    uint32_t* sVh = sm + 9216;
    uint32_t* sVl = sm + 11520;
    __nv_bfloat16* sVh16 = (__nv_bfloat16*)sVh;
    __nv_bfloat16* sVl16 = (__nv_bfloat16*)sVl;

    int z  = blockIdx.y;
    int b  = z >> 4, h = z & 15;
    int m0 = (3 - (int)blockIdx.x) * 128;

    int tid = threadIdx.x, lane = tid & 31, wid = tid >> 5;
    int wm = wid >> 2, wn = wid & 3, lq = lane >> 2, tq = lane & 3;

    const uint32_t* pwh = (const uint32_t*)(g_phi + (size_t)z * S_ * S_);
    const uint32_t* pwl = (const uint32_t*)(g_plo + (size_t)z * S_ * S_);
    const uint32_t* vwh = (const uint32_t*)(g_vhh + (size_t)z * S_ * DH_);
    const uint32_t* vwl = (const uint32_t*)(g_vhl + (size_t)z * S_ * DH_);

    float acc[4][2][4];
    #pragma unroll
    for (int mt = 0; mt < 4; mt++)
        #pragma unroll
        for (int nt = 0; nt < 2; nt++)
            #pragma unroll
            for (int e = 0; e < 4; e++) acc[mt][nt][e] = 0.f;

    int nchunks = m0 / 64 + 2;

    for (int c = 0; c < nchunks; c++) {
        int k0 = c * 64;
        {
            int row = tid >> 1, hf = tid & 1;
            int gofs = (m0 + row) * 256 + k0 / 2 + hf * 16;
            int so = row * PADS + hf * 16;
            #pragma unroll
            for (int qd = 0; qd < 4; qd++) {
                *(uint4*)(sPh + so + qd * 4) = *(const uint4*)(pwh + gofs + qd * 4);
                *(uint4*)(sPl + so + qd * 4) = *(const uint4*)(pwl + gofs + qd * 4);
            }
        }
        {
            int r  = tid >> 2;
            int w0 = (tid & 3) * 8;
            #pragma unroll
            for (int qd = 0; qd < 2; qd++) {
                uint4 vv = *(const uint4*)(vwh + (k0 + r) * 32 + w0 + qd * 4);
                uint32_t wv[4] = {vv.x, vv.y, vv.z, vv.w};
                #pragma unroll
                for (int q2 = 0; q2 < 4; q2++) {
                    int d0 = (w0 + qd * 4 + q2) * 2;
                    __nv_bfloat162 pr = *(__nv_bfloat162*)&wv[q2];
                    sVh16[d0 * 72 + r]       = pr.x;
                    sVh16[(d0 + 1) * 72 + r] = pr.y;
                }
                vv = *(const uint4*)(vwl + (k0 + r) * 32 + w0 + qd * 4);
                wv[0] = vv.x; wv[1] = vv.y; wv[2] = vv.z; wv[3] = vv.w;
                #pragma unroll
                for (int q2 = 0; q2 < 4; q2++) {
                    int d0 = (w0 + qd * 4 + q2) * 2;
                    __nv_bfloat162 pr = *(__nv_bfloat162*)&wv[q2];
                    sVl16[d0 * 72 + r]       = pr.x;
                    sVl16[(d0 + 1) * 72 + r] = pr.y;
                }
            }
        }
        __syncthreads();

        #pragma unroll
        for (int ks = 0; ks < 4; ks++) {
            int kofs = ks * 8 + tq;
            uint32_t bh[2][2], bl[2][2];
            #pragma unroll
            for (int nt = 0; nt < 2; nt++) {
                int bi = (wn * 16 + nt * 8 + lq) * PADS + kofs;
                bh[nt][0] = sVh[bi]; bh[nt][1] = sVh[bi + 4];
                bl[nt][0] = sVl[bi]; bl[nt][1] = sVl[bi + 4];
            }
            #pragma unroll
            for (int mt = 0; mt < 4; mt++) {
                int ai = (wm * 64 + mt * 16 + lq) * PADS + kofs;
                uint32_t ah0 = sPh[ai],     ah1 = sPh[ai + 8 * PADS];
                uint32_t ah2 = sPh[ai + 4], ah3 = sPh[ai + 8 * PADS + 4];
                uint32_t al0 = sPl[ai],     al1 = sPl[ai + 8 * PADS];
                uint32_t al2 = sPl[ai + 4], al3 = sPl[ai + 8 * PADS + 4];
                #pragma unroll
                for (int nt = 0; nt < 2; nt++) {
                    mma_bf16(acc[mt][nt], ah0, ah1, ah2, ah3, bh[nt][0], bh[nt][1]);
                    mma_bf16(acc[mt][nt], al0, al1, al2, al3, bh[nt][0], bh[nt][1]);
                    mma_bf16(acc[mt][nt], ah0, ah1, ah2, ah3, bl[nt][0], bl[nt][1]);
                }
            }
        }
        __syncthreads();
    }

    #pragma unroll
    for (int mt = 0; mt < 4; mt++) {
        #pragma unroll
        for (int nt = 0; nt < 2; nt++) {
            int d = wn * 16 + nt * 8 + tq * 2;
            #pragma unroll
            for (int hf = 0; hf < 2; hf++) {
                int i = m0 + wm * 64 + mt * 16 + lq + hf * 8;
                *(float2*)&g_att[((size_t)b * S_ + i) * D_ + h * DH_ + d] =
                    make_float2(acc[mt][nt][hf * 2], acc[mt][nt][hf * 2 + 1]);
            }
        }
    }
}

// ==================================================================================
extern "C" void kernel_launch(void* const* d_in, const int* in_sizes, int n_in,
                              void* d_out, int out_size)
{
    const float* q      = (const float*)d_in[0];
    const float* k      = (const float*)d_in[1];
    const float* v      = (const float*)d_in[2];
    const float* pdiff  = (const float*)d_in[3];
    const float* Wk     = (const float*)d_in[4];
    const float* bk     = (const float*)d_in[5];
    const float* Wv     = (const float*)d_in[6];
    const float* bv     = (const float*)d_in[7];
    const float* Wo     = (const float*)d_in[8];
    const float* bo     = (const float*)d_in[9];
    const float* gammas = (const float*)d_in[10];
    float* out = (float*)d_out;

    float* att;
    cudaGetSymbolAddress((void**)&att, g_att);

    const int GSM = 2 * STG2 * 4;   // 61440 B

    cudaFuncSetAttribute(gemm_qkv,   cudaFuncAttributeMaxDynamicSharedMemorySize, GSM);
    cudaFuncSetAttribute(gemm_out,   cudaFuncAttributeMaxDynamicSharedMemorySize, GSM);
    cudaFuncSetAttribute(scores_mma, cudaFuncAttributeMaxDynamicSharedMemorySize, 73728);
    cudaFuncSetAttribute(pv_mma,     cudaFuncAttributeMaxDynamicSharedMemorySize, 55296);

    gemm_qkv<<<dim3(8, 64, 3), 256, GSM>>>(q, k, v, Wk, bk, Wv, bv);

    dv_kernel<<<(B_ * S_ * S_) / 256, 256>>>(pdiff);

    scores_mma<<<dim3(10, BH_), 256, 73728>>>();

    row_kernel<<<dim3(S_ / 8, BH_), 256>>>(gammas);

    pv_mma<<<dim3(4, BH_), 256, 55296>>>();

    gemm_out<<<dim3(8, 64), 256, GSM>>>(att, Wo, bo, out);
}

// round 7
// speedup vs baseline: 1.4061x; 1.1230x over previous
#include <cuda_runtime.h>
#include <cuda_bf16.h>
#include <math.h>
#include <stdint.h>

#define B_  8
#define S_  512
#define D_  1024
#define H_  16
#define DH_ 64
#define BH_ 128

// ---------------- scratch (device globals; no runtime allocation) ----------------
__device__ float g_sc [(size_t)BH_*S_*S_];            // fp32 scores
__device__ float g_att[(size_t)B_*S_*D_];             // attention out, concat [B,S,D]
__device__ float g_dv [(size_t)B_*S_*S_];             // exp(sigmoid(pdiff))
__device__ __nv_bfloat16 g_qhh[(size_t)BH_*S_*DH_], g_qhl[(size_t)BH_*S_*DH_];
__device__ __nv_bfloat16 g_khh[(size_t)BH_*S_*DH_], g_khl[(size_t)BH_*S_*DH_];
__device__ __nv_bfloat16 g_vhh[(size_t)BH_*S_*DH_], g_vhl[(size_t)BH_*S_*DH_];
__device__ __nv_bfloat16 g_phi[(size_t)BH_*S_*S_],  g_plo[(size_t)BH_*S_*S_];

// ======================= warp-level bf16 MMA ======================================
__device__ __forceinline__ void mma_bf16(float* c, uint32_t a0, uint32_t a1,
                                         uint32_t a2, uint32_t a3,
                                         uint32_t b0, uint32_t b1) {
    asm volatile(
        "mma.sync.aligned.m16n8k16.row.col.f32.bf16.bf16.f32 "
        "{%0,%1,%2,%3}, {%4,%5,%6,%7}, {%8,%9}, {%0,%1,%2,%3};"
        : "+f"(c[0]), "+f"(c[1]), "+f"(c[2]), "+f"(c[3])
        : "r"(a0), "r"(a1), "r"(a2), "r"(a3), "r"(b0), "r"(b1));
}
__device__ __forceinline__ uint32_t pack_bf16(float x, float y) {
    __nv_bfloat162 t = __floats2bfloat162_rn(x, y);
    return *(uint32_t*)&t;
}
__device__ __forceinline__ void split4(float4 v, uint32_t& h0, uint32_t& h1,
                                       uint32_t& l0, uint32_t& l1) {
    h0 = pack_bf16(v.x, v.y);
    h1 = pack_bf16(v.z, v.w);
    __nv_bfloat162 hh0 = *(__nv_bfloat162*)&h0;
    __nv_bfloat162 hh1 = *(__nv_bfloat162*)&h1;
    l0 = pack_bf16(v.x - __bfloat162float(hh0.x), v.y - __bfloat162float(hh0.y));
    l1 = pack_bf16(v.z - __bfloat162float(hh1.x), v.w - __bfloat162float(hh1.y));
}

// ==================================================================================
// Double-buffered bf16x3 GEMM (R4 config):  C = A[M,K] * W[N,K]^T + bias
// Block 128x128, BK=32, 8 warps (2x4), warp tile 64x32, PAD 20 words.
// ==================================================================================
#define PADW 20
#define STG  10240

template<bool PAIR>
__device__ __forceinline__ void gemm_body(const float* __restrict__ A,
                                          const float* __restrict__ W,
                                          const float* __restrict__ bias,
                                          float* outF, __nv_bfloat16* outH,
                                          __nv_bfloat16* outL,
                                          int m0, int n0, uint32_t* dsm)
{
    int tid = threadIdx.x, lane = tid & 31, wid = tid >> 5;
    int wm = wid >> 2, wn = wid & 3;
    int lq = lane >> 2, tq = lane & 3;

    float acc[4][4][4];
    #pragma unroll
    for (int mt = 0; mt < 4; mt++)
        #pragma unroll
        for (int nt = 0; nt < 4; nt++)
            #pragma unroll
            for (int e = 0; e < 4; e++) acc[mt][nt][e] = 0.f;

    int rowr[4], cqr[4], wofs[4];
    #pragma unroll
    for (int r = 0; r < 4; r++) {
        int g = tid + r * 256;
        rowr[r] = g >> 3;
        cqr[r]  = g & 7;
        wofs[r] = rowr[r] * PADW + cqr[r] * 2;
    }

    float4 va[4], vb[4];
    #pragma unroll
    for (int r = 0; r < 4; r++) {
        va[r] = *(const float4*)(A + (size_t)(m0 + rowr[r]) * D_ + cqr[r] * 4);
        vb[r] = *(const float4*)(W + (size_t)(n0 + rowr[r]) * D_ + cqr[r] * 4);
    }

    auto cvtstore = [&](uint32_t* base) {
        #pragma unroll
        for (int r = 0; r < 4; r++) {
            uint32_t h0, h1, l0, l1;
            split4(va[r], h0, h1, l0, l1);
            base[wofs[r]]        = h0; base[wofs[r] + 1]        = h1;
            base[2560 + wofs[r]] = l0; base[2560 + wofs[r] + 1] = l1;
            split4(vb[r], h0, h1, l0, l1);
            base[5120 + wofs[r]] = h0; base[5120 + wofs[r] + 1] = h1;
            base[7680 + wofs[r]] = l0; base[7680 + wofs[r] + 1] = l1;
        }
    };

    cvtstore(dsm);
    int stage = 0;

    for (int kc = 0; kc < 32; kc++) {
        __syncthreads();
        if (kc < 31) {
            int k0 = (kc + 1) * 32;
            #pragma unroll
            for (int r = 0; r < 4; r++) {
                va[r] = *(const float4*)(A + (size_t)(m0 + rowr[r]) * D_ + k0 + cqr[r] * 4);
                vb[r] = *(const float4*)(W + (size_t)(n0 + rowr[r]) * D_ + k0 + cqr[r] * 4);
            }
        }
        uint32_t* base = dsm + stage * STG;
        #pragma unroll
        for (int ks = 0; ks < 2; ks++) {
            int kofs = ks * 8 + tq;
            uint32_t bh[4][2], bl[4][2];
            #pragma unroll
            for (int nt = 0; nt < 4; nt++) {
                int bi = (wn * 32 + nt * 8 + lq) * PADW + kofs;
                bh[nt][0] = base[5120 + bi]; bh[nt][1] = base[5120 + bi + 4];
                bl[nt][0] = base[7680 + bi]; bl[nt][1] = base[7680 + bi + 4];
            }
            #pragma unroll
            for (int mt = 0; mt < 4; mt++) {
                int ai = (wm * 64 + mt * 16 + lq) * PADW + kofs;
                uint32_t ah0 = base[ai],            ah1 = base[ai + 8 * PADW];
                uint32_t ah2 = base[ai + 4],        ah3 = base[ai + 8 * PADW + 4];
                uint32_t al0 = base[2560 + ai],     al1 = base[2560 + ai + 8 * PADW];
                uint32_t al2 = base[2560 + ai + 4], al3 = base[2560 + ai + 8 * PADW + 4];
                #pragma unroll
                for (int nt = 0; nt < 4; nt++) {
                    mma_bf16(acc[mt][nt], ah0, ah1, ah2, ah3, bh[nt][0], bh[nt][1]);
                    mma_bf16(acc[mt][nt], ah0, ah1, ah2, ah3, bl[nt][0], bl[nt][1]);
                    mma_bf16(acc[mt][nt], al0, al1, al2, al3, bh[nt][0], bh[nt][1]);
                }
            }
        }
        if (kc < 31) cvtstore(dsm + (stage ^ 1) * STG);
        stage ^= 1;
    }

    #pragma unroll
    for (int mt = 0; mt < 4; mt++) {
        #pragma unroll
        for (int nt = 0; nt < 4; nt++) {
            int n = n0 + wn * 32 + nt * 8 + tq * 2;
            float b0v = __ldg(bias + n), b1v = __ldg(bias + n + 1);
            #pragma unroll
            for (int hf = 0; hf < 2; hf++) {
                int m = m0 + wm * 64 + mt * 16 + lq + hf * 8;
                float v0 = acc[mt][nt][hf * 2 + 0] + b0v;
                float v1 = acc[mt][nt][hf * 2 + 1] + b1v;
                if (PAIR) {
                    int bb = m / S_, srow = m % S_;
                    int h = n >> 6, d = n & 63;
                    size_t idx = (((size_t)bb * H_ + h) * S_ + srow) * DH_ + d;
                    __nv_bfloat16 h0 = __float2bfloat16(v0);
                    __nv_bfloat16 h1 = __float2bfloat16(v1);
                    __nv_bfloat162 hv; hv.x = h0; hv.y = h1;
                    __nv_bfloat162 lv;
                    lv.x = __float2bfloat16(v0 - __bfloat162float(h0));
                    lv.y = __float2bfloat16(v1 - __bfloat162float(h1));
                    *(__nv_bfloat162*)(outH + idx) = hv;
                    *(__nv_bfloat162*)(outL + idx) = lv;
                } else {
                    *(float2*)&outF[(size_t)m * D_ + n] = make_float2(v0, v1);
                }
            }
        }
    }
}

__global__ __launch_bounds__(256, 1)
void gemm_qkv(const float* __restrict__ q, const float* __restrict__ k,
              const float* __restrict__ v, const float* __restrict__ Wk,
              const float* __restrict__ bk, const float* __restrict__ Wv,
              const float* __restrict__ bv)
{
    extern __shared__ __align__(16) uint32_t dsm[];
    int z = blockIdx.z;
    const float* A    = (z == 0) ? q : (z == 1) ? k : v;
    const float* W    = (z == 2) ? Wv : Wk;
    const float* bias = (z == 2) ? bv : bk;
    __nv_bfloat16* oh = (z == 0) ? g_qhh : (z == 1) ? g_khh : g_vhh;
    __nv_bfloat16* ol = (z == 0) ? g_qhl : (z == 1) ? g_khl : g_vhl;
    gemm_body<true>(A, W, bias, nullptr, oh, ol,
                    blockIdx.y * 128, blockIdx.x * 128, dsm);
}

__global__ __launch_bounds__(256, 1)
void gemm_out(const float* __restrict__ A, const float* __restrict__ W,
              const float* __restrict__ bias, float* __restrict__ out)
{
    extern __shared__ __align__(16) uint32_t dsm[];
    gemm_body<false>(A, W, bias, out, nullptr, nullptr,
                     blockIdx.y * 128, blockIdx.x * 128, dsm);
}

// ==================================================================================
// Scores via MMA (R4, unchanged): per head z, tile 128x128, causal (10 of 16).
// ==================================================================================
#define PADS 36

__global__ __launch_bounds__(256, 1)
void scores_mma()
{
    extern __shared__ __align__(16) uint32_t sm[];
    uint32_t* sQh = sm;
    uint32_t* sQl = sm + 4608;
    uint32_t* sKh = sm + 9216;
    uint32_t* sKl = sm + 13824;

    int z = blockIdx.y;
    int t = blockIdx.x;
    int mi = (t < 1) ? 0 : (t < 3) ? 1 : (t < 6) ? 2 : 3;
    int ni = t - mi * (mi + 1) / 2;
    int m0 = mi * 128, n0 = ni * 128;

    int tid = threadIdx.x, lane = tid & 31, wid = tid >> 5;
    int wm = wid >> 2, wn = wid & 3, lq = lane >> 2, tq = lane & 3;

    const uint32_t* qh = (const uint32_t*)(g_qhh + (size_t)z * S_ * DH_);
    const uint32_t* ql = (const uint32_t*)(g_qhl + (size_t)z * S_ * DH_);
    const uint32_t* kh = (const uint32_t*)(g_khh + (size_t)z * S_ * DH_);
    const uint32_t* kl = (const uint32_t*)(g_khl + (size_t)z * S_ * DH_);

    {
        int row = tid >> 1, hf = tid & 1;
        int gq = (m0 + row) * 32 + hf * 16;
        int gk = (n0 + row) * 32 + hf * 16;
        int so = row * PADS + hf * 16;
        #pragma unroll
        for (int qd = 0; qd < 4; qd++) {
            *(uint4*)(sQh + so + qd * 4) = *(const uint4*)(qh + gq + qd * 4);
            *(uint4*)(sQl + so + qd * 4) = *(const uint4*)(ql + gq + qd * 4);
            *(uint4*)(sKh + so + qd * 4) = *(const uint4*)(kh + gk + qd * 4);
            *(uint4*)(sKl + so + qd * 4) = *(const uint4*)(kl + gk + qd * 4);
        }
    }
    __syncthreads();

    float acc[4][4][4];
    #pragma unroll
    for (int mt = 0; mt < 4; mt++)
        #pragma unroll
        for (int nt = 0; nt < 4; nt++)
            #pragma unroll
            for (int e = 0; e < 4; e++) acc[mt][nt][e] = 0.f;

    #pragma unroll
    for (int ks = 0; ks < 4; ks++) {
        int kofs = ks * 8 + tq;
        uint32_t bh[4][2], bl[4][2];
        #pragma unroll
        for (int nt = 0; nt < 4; nt++) {
            int bi = (wn * 32 + nt * 8 + lq) * PADS + kofs;
            bh[nt][0] = sKh[bi]; bh[nt][1] = sKh[bi + 4];
            bl[nt][0] = sKl[bi]; bl[nt][1] = sKl[bi + 4];
        }
        #pragma unroll
        for (int mt = 0; mt < 4; mt++) {
            int ai = (wm * 64 + mt * 16 + lq) * PADS + kofs;
            uint32_t ah0 = sQh[ai],     ah1 = sQh[ai + 8 * PADS];
            uint32_t ah2 = sQh[ai + 4], ah3 = sQh[ai + 8 * PADS + 4];
            uint32_t al0 = sQl[ai],     al1 = sQl[ai + 8 * PADS];
            uint32_t al2 = sQl[ai + 4], al3 = sQl[ai + 8 * PADS + 4];
            #pragma unroll
            for (int nt = 0; nt < 4; nt++) {
                mma_bf16(acc[mt][nt], ah0, ah1, ah2, ah3, bh[nt][0], bh[nt][1]);
                mma_bf16(acc[mt][nt], ah0, ah1, ah2, ah3, bl[nt][0], bl[nt][1]);
                mma_bf16(acc[mt][nt], al0, al1, al2, al3, bh[nt][0], bh[nt][1]);
            }
        }
    }

    float* C = g_sc + (size_t)z * S_ * S_;
    #pragma unroll
    for (int mt = 0; mt < 4; mt++) {
        #pragma unroll
        for (int nt = 0; nt < 4; nt++) {
            int j = n0 + wn * 32 + nt * 8 + tq * 2;
            #pragma unroll
            for (int hf = 0; hf < 2; hf++) {
                int i = m0 + wm * 64 + mt * 16 + lq + hf * 8;
                *(float2*)&C[(size_t)i * S_ + j] =
                    make_float2(acc[mt][nt][hf * 2] * 0.125f,
                                acc[mt][nt][hf * 2 + 1] * 0.125f);
            }
        }
    }
}

// ==================================================================================
// dv precompute
// ==================================================================================
__global__ __launch_bounds__(256)
void dv_kernel(const float* __restrict__ pdiff)
{
    size_t idx = (size_t)blockIdx.x * 256 + threadIdx.x;
    float x = pdiff[idx];
    float sig = 1.f / (1.f + __expf(-x));
    g_dv[idx] = __expf(sig);
}

// ==================================================================================
// Row kernel: warp per row. No max-shift (validated R5/R6), but with a dedicated
// BATCHED load pass first (restores MLP=16; the serial scan runs on registers).
// ==================================================================================
__global__ __launch_bounds__(256)
void row_kernel(const float* __restrict__ gammas)
{
    int warp = threadIdx.x >> 5, lane = threadIdx.x & 31;
    int i = blockIdx.x * 8 + warp;
    int z = blockIdx.y;
    int b = z >> 4, h = z & 15;

    const float* row   = g_sc + ((size_t)z * S_ + i) * S_;
    const float* dvrow = g_dv + ((size_t)b * S_ + i) * S_;

    int nch = (i >> 5) + 1;
    float scv[16], s2v[16];

    // pass 0: batched loads (all independent -> deep MLP)
    #pragma unroll
    for (int c = 0; c < 16; c++)
        if (c < nch) scv[c] = row[c * 32 + lane];

    // pass 1: exp + inclusive scan (registers only)
    float run = 0.f;
    #pragma unroll
    for (int c = 0; c < 16; c++) {
        if (c < nch) {
            int j = c * 32 + lane;
            float p = (j <= i) ? __expf(scv[c]) : 0.f;
            float s = p;
            #pragma unroll
            for (int d = 1; d < 32; d <<= 1) {
                float tt = __shfl_up_sync(0xFFFFFFFFu, s, d);
                if (lane >= d) s += tt;
            }
            s2v[c] = run + s;
            run += __shfl_sync(0xFFFFFFFFu, s, 31);
        }
    }
    float tot  = run;
    float rtot = 1.f / fmaxf(tot, 1e-30f);

    float g = gammas[h];
    float gamma = -log1pf(__expf(g));

    // pass 2: batched dv loads
    float dvv[16];
    #pragma unroll
    for (int c = 0; c < 16; c++)
        if (c < nch) dvv[c] = dvrow[c * 32 + lane];

    // pass 3: decay reweight + exp + sum
    float sum2 = 0.f;
    #pragma unroll
    for (int c = 0; c < 16; c++) {
        if (c < nch) {
            int j = c * 32 + lane;
            float rem  = fmaxf(tot - s2v[c], 0.f) * rtot;
            float pos  = (float)(i - j);
            float dist = sqrtf(fmaxf(rem * pos, 0.f));
            float eff  = __expf(dist * gamma * dvv[c]);
            eff = fminf(fmaxf(eff, 1e-5f), 1e5f);
            float s2 = scv[c] * eff;
            float e2 = (j <= i) ? __expf(s2) : 0.f;
            s2v[c] = e2;
            sum2 += e2;
        }
    }
    #pragma unroll
    for (int o = 16; o > 0; o >>= 1) sum2 += __shfl_xor_sync(0xFFFFFFFFu, sum2, o);

    float rs = (i == 0) ? 0.f : 1.f / sum2;

    __nv_bfloat16* ph = g_phi + ((size_t)z * S_ + i) * S_;
    __nv_bfloat16* pl = g_plo + ((size_t)z * S_ + i) * S_;
    int nwrite = ((i >> 7) + 1) * 4;
    #pragma unroll
    for (int c = 0; c < 16; c++) {
        int j = c * 32 + lane;
        if (c < nch || c < nwrite) {
            float p = (c < nch && j <= i) ? s2v[c] * rs : 0.f;
            __nv_bfloat16 hh = __float2bfloat16(p);
            ph[j] = hh;
            pl[j] = __float2bfloat16(p - __bfloat162float(hh));
        }
    }
}

// ==================================================================================
// PV via MMA (R4, unchanged): out[i,d] = sum_j P[i,j] V[j,d]. 128(M) x 64(N).
// ==================================================================================
__global__ __launch_bounds__(256, 1)
void pv_mma()
{
    extern __shared__ __align__(16) uint32_t sm[];
    uint32_t* sPh = sm;
    uint32_t* sPl = sm + 4608;
    uint32_t* sVh = sm + 9216;
    uint32_t* sVl = sm + 11520;
    __nv_bfloat16* sVh16 = (__nv_bfloat16*)sVh;
    __nv_bfloat16* sVl16 = (__nv_bfloat16*)sVl;

    int z  = blockIdx.y;
    int b  = z >> 4, h = z & 15;
    int m0 = (3 - (int)blockIdx.x) * 128;

    int tid = threadIdx.x, lane = tid & 31, wid = tid >> 5;
    int wm = wid >> 2, wn = wid & 3, lq = lane >> 2, tq = lane & 3;

    const uint32_t* pwh = (const uint32_t*)(g_phi + (size_t)z * S_ * S_);
    const uint32_t* pwl = (const uint32_t*)(g_plo + (size_t)z * S_ * S_);
    const uint32_t* vwh = (const uint32_t*)(g_vhh + (size_t)z * S_ * DH_);
    const uint32_t* vwl = (const uint32_t*)(g_vhl + (size_t)z * S_ * DH_);

    float acc[4][2][4];
    #pragma unroll
    for (int mt = 0; mt < 4; mt++)
        #pragma unroll
        for (int nt = 0; nt < 2; nt++)
            #pragma unroll
            for (int e = 0; e < 4; e++) acc[mt][nt][e] = 0.f;

    int nchunks = m0 / 64 + 2;

    for (int c = 0; c < nchunks; c++) {
        int k0 = c * 64;
        {
            int row = tid >> 1, hf = tid & 1;
            int gofs = (m0 + row) * 256 + k0 / 2 + hf * 16;
            int so = row * PADS + hf * 16;
            #pragma unroll
            for (int qd = 0; qd < 4; qd++) {
                *(uint4*)(sPh + so + qd * 4) = *(const uint4*)(pwh + gofs + qd * 4);
                *(uint4*)(sPl + so + qd * 4) = *(const uint4*)(pwl + gofs + qd * 4);
            }
        }
        {
            int r  = tid >> 2;
            int w0 = (tid & 3) * 8;
            #pragma unroll
            for (int qd = 0; qd < 2; qd++) {
                uint4 vv = *(const uint4*)(vwh + (k0 + r) * 32 + w0 + qd * 4);
                uint32_t wv[4] = {vv.x, vv.y, vv.z, vv.w};
                #pragma unroll
                for (int q2 = 0; q2 < 4; q2++) {
                    int d0 = (w0 + qd * 4 + q2) * 2;
                    __nv_bfloat162 pr = *(__nv_bfloat162*)&wv[q2];
                    sVh16[d0 * 72 + r]       = pr.x;
                    sVh16[(d0 + 1) * 72 + r] = pr.y;
                }
                vv = *(const uint4*)(vwl + (k0 + r) * 32 + w0 + qd * 4);
                wv[0] = vv.x; wv[1] = vv.y; wv[2] = vv.z; wv[3] = vv.w;
                #pragma unroll
                for (int q2 = 0; q2 < 4; q2++) {
                    int d0 = (w0 + qd * 4 + q2) * 2;
                    __nv_bfloat162 pr = *(__nv_bfloat162*)&wv[q2];
                    sVl16[d0 * 72 + r]       = pr.x;
                    sVl16[(d0 + 1) * 72 + r] = pr.y;
                }
            }
        }
        __syncthreads();

        #pragma unroll
        for (int ks = 0; ks < 4; ks++) {
            int kofs = ks * 8 + tq;
            uint32_t bh[2][2], bl[2][2];
            #pragma unroll
            for (int nt = 0; nt < 2; nt++) {
                int bi = (wn * 16 + nt * 8 + lq) * PADS + kofs;
                bh[nt][0] = sVh[bi]; bh[nt][1] = sVh[bi + 4];
                bl[nt][0] = sVl[bi]; bl[nt][1] = sVl[bi + 4];
            }
            #pragma unroll
            for (int mt = 0; mt < 4; mt++) {
                int ai = (wm * 64 + mt * 16 + lq) * PADS + kofs;
                uint32_t ah0 = sPh[ai],     ah1 = sPh[ai + 8 * PADS];
                uint32_t ah2 = sPh[ai + 4], ah3 = sPh[ai + 8 * PADS + 4];
                uint32_t al0 = sPl[ai],     al1 = sPl[ai + 8 * PADS];
                uint32_t al2 = sPl[ai + 4], al3 = sPl[ai + 8 * PADS + 4];
                #pragma unroll
                for (int nt = 0; nt < 2; nt++) {
                    mma_bf16(acc[mt][nt], ah0, ah1, ah2, ah3, bh[nt][0], bh[nt][1]);
                    mma_bf16(acc[mt][nt], al0, al1, al2, al3, bh[nt][0], bh[nt][1]);
                    mma_bf16(acc[mt][nt], ah0, ah1, ah2, ah3, bl[nt][0], bl[nt][1]);
                }
            }
        }
        __syncthreads();
    }

    #pragma unroll
    for (int mt = 0; mt < 4; mt++) {
        #pragma unroll
        for (int nt = 0; nt < 2; nt++) {
            int d = wn * 16 + nt * 8 + tq * 2;
            #pragma unroll
            for (int hf = 0; hf < 2; hf++) {
                int i = m0 + wm * 64 + mt * 16 + lq + hf * 8;
                *(float2*)&g_att[((size_t)b * S_ + i) * D_ + h * DH_ + d] =
                    make_float2(acc[mt][nt][hf * 2], acc[mt][nt][hf * 2 + 1]);
            }
        }
    }
}

// ==================================================================================
extern "C" void kernel_launch(void* const* d_in, const int* in_sizes, int n_in,
                              void* d_out, int out_size)
{
    const float* q      = (const float*)d_in[0];
    const float* k      = (const float*)d_in[1];
    const float* v      = (const float*)d_in[2];
    const float* pdiff  = (const float*)d_in[3];
    const float* Wk     = (const float*)d_in[4];
    const float* bk     = (const float*)d_in[5];
    const float* Wv     = (const float*)d_in[6];
    const float* bv     = (const float*)d_in[7];
    const float* Wo     = (const float*)d_in[8];
    const float* bo     = (const float*)d_in[9];
    const float* gammas = (const float*)d_in[10];
    float* out = (float*)d_out;

    float* att;
    cudaGetSymbolAddress((void**)&att, g_att);

    cudaFuncSetAttribute(gemm_qkv,   cudaFuncAttributeMaxDynamicSharedMemorySize, 81920);
    cudaFuncSetAttribute(gemm_out,   cudaFuncAttributeMaxDynamicSharedMemorySize, 81920);
    cudaFuncSetAttribute(scores_mma, cudaFuncAttributeMaxDynamicSharedMemorySize, 73728);
    cudaFuncSetAttribute(pv_mma,     cudaFuncAttributeMaxDynamicSharedMemorySize, 55296);

    gemm_qkv<<<dim3(8, 32, 3), 256, 81920>>>(q, k, v, Wk, bk, Wv, bv);

    dv_kernel<<<(B_ * S_ * S_) / 256, 256>>>(pdiff);

    scores_mma<<<dim3(10, BH_), 256, 73728>>>();

    row_kernel<<<dim3(S_ / 8, BH_), 256>>>(gammas);

    pv_mma<<<dim3(4, BH_), 256, 55296>>>();

    gemm_out<<<dim3(8, 32), 256, 81920>>>(att, Wo, bo, out);
}